// round 13
// baseline (speedup 1.0000x reference)
#include <cuda_runtime.h>
#include <cuda_bf16.h>
#include <math.h>

#define BB 2
#define NN 1024
#define TOK (BB*NN)
#define DIM 1024
#define DQK 128
#define NKEY 256
#define TOPK 32
#define DV 512
#define KCONV 5
#define OUT_MAIN (TOK*1024)

__device__ float g_invrms[TOK];
__device__ float g_x2[TOK*DIM];
__device__ float g_q[TOK*DQK];
__device__ float g_sc[TOK*1024];

__device__ __forceinline__ float fsign(float a, float b){ return (b >= 0.f) ? fabsf(a) : -fabsf(a); }
__device__ __forceinline__ unsigned sortable_f(float f){
    unsigned u = __float_as_uint(f);
    return (u & 0x80000000u) ? ~u : (u | 0x80000000u);
}
__device__ __forceinline__ float unsortable_f(unsigned s){
    unsigned u = (s & 0x80000000u) ? (s ^ 0x80000000u) : ~s;
    return __uint_as_float(u);
}
__device__ __forceinline__ unsigned long long pack_key(float v, unsigned idx){
    return (((unsigned long long)sortable_f(v)) << 32) | (unsigned long long)(0xFFFFFFFFu - idx);
}

// ---------------- LAPACK slasv2 port ----------------
__device__ void slasv2_dev(float f, float g, float h,
                           float& ssmin, float& ssmax,
                           float& snr, float& csr, float& snl, float& csl)
{
    float ft=f, fa=fabsf(f), ht=h, ha=fabsf(h);
    int pmax = 1;
    bool swp = (ha > fa);
    if (swp){ pmax = 3; float t; t=ft; ft=ht; ht=t; t=fa; fa=ha; ha=t; }
    float gt=g, ga=fabsf(g);
    float clt=0.f, crt=0.f, slt=0.f, srt=0.f;
    if (ga == 0.f){
        ssmin = ha; ssmax = fa; clt=1.f; crt=1.f; slt=0.f; srt=0.f;
    } else {
        bool gasmal = true;
        if (ga > fa){
            pmax = 2;
            if ((fa/ga) < 5.9604645e-08f){
                gasmal = false;
                ssmax = ga;
                ssmin = (ha > 1.f) ? (fa/(ga/ha)) : ((fa/ga)*ha);
                clt = 1.f; slt = ht/gt; srt = 1.f; crt = ft/gt;
            }
        }
        if (gasmal){
            float d_ = fa - ha;
            float l  = (d_ == fa) ? 1.f : d_/fa;
            float m  = gt/ft;
            float t  = 2.f - l;
            float mm = m*m, tt = t*t;
            float s  = sqrtf(tt + mm);
            float r_ = (l == 0.f) ? fabsf(m) : sqrtf(l*l + mm);
            float a_ = 0.5f*(s + r_);
            ssmin = ha/a_;
            ssmax = fa*a_;
            if (mm == 0.f){
                t = (l == 0.f) ? (fsign(2.f, ft)*fsign(1.f, gt))
                               : (gt/fsign(d_, ft) + m/t);
            } else {
                t = (m/(s + t) + m/(r_ + l))*(1.f + a_);
            }
            float l2 = sqrtf(t*t + 4.f);
            crt = 2.f/l2;
            srt = t/l2;
            clt = (crt + srt*m)/a_;
            slt = (ht/ft)*srt/a_;
        }
    }
    if (swp){ csl = srt; snl = crt; csr = slt; snr = clt; }
    else    { csl = clt; snl = slt; csr = crt; snr = srt; }
    float ts = 0.f;
    if (pmax == 1) ts = fsign(1.f, csr)*fsign(1.f, csl)*fsign(1.f, f);
    if (pmax == 2) ts = fsign(1.f, snr)*fsign(1.f, csl)*fsign(1.f, g);
    if (pmax == 3) ts = fsign(1.f, snr)*fsign(1.f, snl)*fsign(1.f, h);
    ssmax = fsign(ssmax, ts);
    ssmin = fsign(ssmin, ts*fsign(1.f, f)*fsign(1.f, h));
}

__device__ void svd2x2(const float* core, int hh, float& u0, float& u1,
                       float& t0, float& t1, float& auxp)
{
    float a = core[hh*4+0], b = core[hh*4+1];
    float c = core[hh*4+2], d = core[hh*4+3];
    float q00=1.f,q01=0.f,q10=0.f,q11=1.f;
    float d1, e1, d2;
    if (c != 0.f){
        float nrm  = sqrtf(a*a + c*c);
        float beta = (a >= 0.f) ? -nrm : nrm;
        float tau  = (beta - a)/beta;
        float v    = c/(a - beta);
        float w    = b + v*d;
        e1 = b - tau*w;
        d2 = d - tau*v*w;
        d1 = beta;
        q00 = 1.f - tau; q01 = -tau*v; q10 = -tau*v; q11 = 1.f - tau*v*v;
    } else { d1 = a; e1 = b; d2 = d; }
    float ssmin, ssmax, snr, csr, snl, csl;
    slasv2_dev(d1, e1, d2, ssmin, ssmax, snr, csr, snl, csl);
    float vt0 = csr, vt1 = snr;
    float s1 = ssmax;
    if (s1 < 0.f){ s1 = -s1; vt0 = -vt0; vt1 = -vt1; }
    float s2 = fabsf(ssmin);
    u0 = q00*csl + q01*snl;
    u1 = q10*csl + q11*snl;
    t0 = vt0;
    t1 = vt1;
    float r = s2 - 0.15f;
    auxp = (r > 0.f) ? r*r : 0.f;
}

// rms over 2 tokens per block + zero-init of g_q (needed for gemm_q atomics)
__global__ void rms_kernel(const float* __restrict__ tokens)
{
    int w2 = threadIdx.x >> 8;            // 0..1: token within block
    int t  = threadIdx.x & 255;
    int tok = blockIdx.x*2 + w2;
    const float4* p = (const float4*)(tokens + (size_t)tok*DIM);
    float4 v = p[t];
    float s = v.x*v.x + v.y*v.y + v.z*v.z + v.w*v.w;
    for (int o = 16; o; o >>= 1) s += __shfl_xor_sync(0xFFFFFFFFu, s, o);
    __shared__ float ws[2][8];
    if ((t & 31) == 0) ws[w2][t >> 5] = s;
    __syncthreads();
    if (t == 0){
        float tt = 0.f;
        #pragma unroll
        for (int i = 0; i < 8; i++) tt += ws[w2][i];
        g_invrms[tok] = rsqrtf(tt*(1.f/1024.f) + 1.1920929e-07f);
    }
    // zero g_q[tok][:] : 32 threads x float4
    if (t < 32)
        *(float4*)(g_q + (size_t)tok*DQK + t*4) = make_float4(0.f,0.f,0.f,0.f);
}

// conv: thread computes 4 consecutive d (float4) x 4 consecutive n
__global__ void conv_kernel(const float* __restrict__ tokens,
                            const float* __restrict__ rms_w,
                            const float* __restrict__ conv_w,
                            const float* __restrict__ conv_b)
{
    int gid = blockIdx.x*256 + threadIdx.x;
    int d4  = gid & (DIM/4 - 1);
    int grp = gid >> 8;
    int ng  = grp & (NN/4 - 1);
    int bb  = grp >> 8;
    int d   = d4*4;
    float4 rw = *(const float4*)(rms_w + d);
    float4 cb = *(const float4*)(conv_b + d);
    float wv[4][KCONV];
    #pragma unroll
    for (int dd = 0; dd < 4; dd++)
        #pragma unroll
        for (int k = 0; k < KCONV; k++) wv[dd][k] = conv_w[(d+dd)*KCONV + k];
    float4 xv[8];
    #pragma unroll
    for (int j = 0; j < 8; j++){
        int nn = ng*4 - 4 + j;
        if (nn >= 0){
            int t2 = (bb << 10) + nn;
            float ir = g_invrms[t2];
            float4 x = *(const float4*)(tokens + (size_t)t2*DIM + d);
            xv[j].x = x.x*ir*rw.x; xv[j].y = x.y*ir*rw.y;
            xv[j].z = x.z*ir*rw.z; xv[j].w = x.w*ir*rw.w;
        } else xv[j] = make_float4(0.f,0.f,0.f,0.f);
    }
    #pragma unroll
    for (int i = 0; i < 4; i++){
        float4 acc = cb;
        #pragma unroll
        for (int k = 0; k < KCONV; k++){
            acc.x += wv[0][k]*xv[i+k].x;
            acc.y += wv[1][k]*xv[i+k].y;
            acc.z += wv[2][k]*xv[i+k].z;
            acc.w += wv[3][k]*xv[i+k].w;
        }
        *(float4*)(g_x2 + (size_t)((bb << 10) + ng*4 + i)*DIM + d) = acc;
    }
}

// GEMM1: g_q += x2 @ wq^T via atomics, split-K=8.  Tile M64 x N128, 8x4 acc.
__global__ __launch_bounds__(256) void gemm_q(const float* __restrict__ A,
                                              const float* __restrict__ B,
                                              float* __restrict__ C)
{
    __shared__ float As[2][16][68];
    __shared__ float Bs[2][16][132];
    int tid = threadIdx.x, tx = tid & 31, ty = tid >> 5;
    int m0 = blockIdx.y*64, k0 = blockIdx.z*128;
    const float* Ab = A + (size_t)m0*DIM + k0;
    const float* Bb = B + k0;
    float acc[8][4];
    #pragma unroll
    for (int i = 0; i < 8; i++)
        #pragma unroll
        for (int j = 0; j < 4; j++) acc[i][j] = 0.f;
    float ra[4], rb[8];
    #pragma unroll
    for (int e = 0; e < 4; e++){ int f = tid + e*256; ra[e] = Ab[(size_t)(f >> 4)*DIM + (f & 15)]; }
    #pragma unroll
    for (int e = 0; e < 8; e++){ int f = tid + e*256; rb[e] = Bb[(size_t)(f >> 4)*DIM + (f & 15)]; }
    #pragma unroll
    for (int e = 0; e < 4; e++){ int f = tid + e*256; As[0][f & 15][f >> 4] = ra[e]; }
    #pragma unroll
    for (int e = 0; e < 8; e++){ int f = tid + e*256; Bs[0][f & 15][f >> 4] = rb[e]; }
    __syncthreads();
    int cur = 0;
    for (int kk = 0; kk < 128; kk += 16){
        bool nxt = (kk + 16) < 128;
        if (nxt){
            #pragma unroll
            for (int e = 0; e < 4; e++){ int f = tid + e*256; ra[e] = Ab[(size_t)(f >> 4)*DIM + kk + 16 + (f & 15)]; }
            #pragma unroll
            for (int e = 0; e < 8; e++){ int f = tid + e*256; rb[e] = Bb[(size_t)(f >> 4)*DIM + kk + 16 + (f & 15)]; }
        }
        #pragma unroll
        for (int k = 0; k < 16; k++){
            float4 a0 = *(const float4*)&As[cur][k][ty*8];
            float4 a1 = *(const float4*)&As[cur][k][ty*8+4];
            float4 b0 = *(const float4*)&Bs[cur][k][tx*4];
            float a[8] = {a0.x,a0.y,a0.z,a0.w,a1.x,a1.y,a1.z,a1.w};
            float b[4] = {b0.x,b0.y,b0.z,b0.w};
            #pragma unroll
            for (int i = 0; i < 8; i++)
                #pragma unroll
                for (int j = 0; j < 4; j++)
                    acc[i][j] += a[i]*b[j];
        }
        if (nxt){
            #pragma unroll
            for (int e = 0; e < 4; e++){ int f = tid + e*256; As[cur^1][f & 15][f >> 4] = ra[e]; }
            #pragma unroll
            for (int e = 0; e < 8; e++){ int f = tid + e*256; Bs[cur^1][f & 15][f >> 4] = rb[e]; }
            __syncthreads();
            cur ^= 1;
        }
    }
    #pragma unroll
    for (int i = 0; i < 8; i++){
        float* Cr = C + (size_t)(m0 + ty*8 + i)*DQK + tx*4;
        #pragma unroll
        for (int j = 0; j < 4; j++) atomicAdd(Cr + j, acc[i][j]);
    }
}

// ln: warp-per-token in-place LN over g_q
__global__ void ln_kernel(const float* __restrict__ qln_w)
{
    int w = threadIdx.x >> 5, l = threadIdx.x & 31;
    int tok = blockIdx.x*8 + w;
    int col = l*4;
    float4 v = *(const float4*)(g_q + (size_t)tok*DQK + col);
    float s = v.x + v.y + v.z + v.w;
    #pragma unroll
    for (int o = 16; o; o >>= 1) s += __shfl_xor_sync(0xFFFFFFFFu, s, o);
    float mu = s * (1.f/128.f);
    float4 dv = {v.x-mu, v.y-mu, v.z-mu, v.w-mu};
    float s2 = dv.x*dv.x + dv.y*dv.y + dv.z*dv.z + dv.w*dv.w;
    #pragma unroll
    for (int o = 16; o; o >>= 1) s2 += __shfl_xor_sync(0xFFFFFFFFu, s2, o);
    float inv = rsqrtf(s2*(1.f/128.f) + 1e-5f);
    float4 qw = *(const float4*)(qln_w + col);
    float4 r = {dv.x*inv*qw.x, dv.y*inv*qw.y, dv.z*inv*qw.z, dv.w*inv*qw.w};
    *(float4*)(g_q + (size_t)tok*DQK + col) = r;
}

// GEMM2: sc = q @ kp^T with fused keys permutation.  Tile M64 x N128, 8x4 acc.
__global__ __launch_bounds__(256) void gemm_sc(const float* __restrict__ A,
                                               const float* __restrict__ keys,
                                               float* __restrict__ C)
{
    __shared__ float As[2][16][68];
    __shared__ float Bs[2][16][132];
    int tid = threadIdx.x, tx = tid & 31, ty = tid >> 5;
    int m0 = blockIdx.y*64, n0 = blockIdx.x*128;
    const float* Ab = A + (size_t)m0*DQK;
    unsigned brow[8];
    #pragma unroll
    for (int e = 0; e < 8; e++){
        int f = tid + e*256;
        int j = n0 + (f >> 4);
        int c = j >> 9, rem = j & 511, m = rem >> 1, r = rem & 1;
        brow[e] = (unsigned)(((c*2 + r)*NKEY + m))*DQK;
    }
    float acc[8][4];
    #pragma unroll
    for (int i = 0; i < 8; i++)
        #pragma unroll
        for (int j = 0; j < 4; j++) acc[i][j] = 0.f;
    float ra[4], rb[8];
    #pragma unroll
    for (int e = 0; e < 4; e++){ int f = tid + e*256; ra[e] = Ab[(size_t)(f >> 4)*DQK + (f & 15)]; }
    #pragma unroll
    for (int e = 0; e < 8; e++){ int f = tid + e*256; rb[e] = keys[brow[e] + (f & 15)]; }
    #pragma unroll
    for (int e = 0; e < 4; e++){ int f = tid + e*256; As[0][f & 15][f >> 4] = ra[e]; }
    #pragma unroll
    for (int e = 0; e < 8; e++){ int f = tid + e*256; Bs[0][f & 15][f >> 4] = rb[e]; }
    __syncthreads();
    int cur = 0;
    for (int kk = 0; kk < 128; kk += 16){
        bool nxt = (kk + 16) < 128;
        if (nxt){
            #pragma unroll
            for (int e = 0; e < 4; e++){ int f = tid + e*256; ra[e] = Ab[(size_t)(f >> 4)*DQK + kk + 16 + (f & 15)]; }
            #pragma unroll
            for (int e = 0; e < 8; e++){ int f = tid + e*256; rb[e] = keys[brow[e] + kk + 16 + (f & 15)]; }
        }
        #pragma unroll
        for (int k = 0; k < 16; k++){
            float4 a0 = *(const float4*)&As[cur][k][ty*8];
            float4 a1 = *(const float4*)&As[cur][k][ty*8+4];
            float4 b0 = *(const float4*)&Bs[cur][k][tx*4];
            float a[8] = {a0.x,a0.y,a0.z,a0.w,a1.x,a1.y,a1.z,a1.w};
            float b[4] = {b0.x,b0.y,b0.z,b0.w};
            #pragma unroll
            for (int i = 0; i < 8; i++)
                #pragma unroll
                for (int j = 0; j < 4; j++)
                    acc[i][j] += a[i]*b[j];
        }
        if (nxt){
            #pragma unroll
            for (int e = 0; e < 4; e++){ int f = tid + e*256; As[cur^1][f & 15][f >> 4] = ra[e]; }
            #pragma unroll
            for (int e = 0; e < 8; e++){ int f = tid + e*256; Bs[cur^1][f & 15][f >> 4] = rb[e]; }
            __syncthreads();
            cur ^= 1;
        }
    }
    #pragma unroll
    for (int i = 0; i < 8; i++){
        float4 v = {acc[i][0], acc[i][1], acc[i][2], acc[i][3]};
        *(float4*)(C + (size_t)(m0 + ty*8 + i)*1024 + n0 + tx*4) = v;
    }
}

// ---------------- block-wide exact top-32 threshold via MSB radix descent ----------------
__device__ unsigned long long radix_select32(const unsigned long long* kv, int npt, int tid,
                                             unsigned* hist, unsigned* sh)
{
    unsigned long long prefix = 0;
    bool act[4] = {true, true, true, true};
    int need = 32;
    int lane = tid & 31, w = tid >> 5;
    for (int shift = 56; shift >= 0; shift -= 8){
        hist[tid] = 0;
        __syncthreads();
        #pragma unroll
        for (int e = 0; e < 4; e++)
            if (e < npt && act[e])
                atomicAdd(&hist[(unsigned)((kv[e] >> shift) & 255)], 1u);
        __syncthreads();
        unsigned h = hist[tid];
        unsigned inc = h;
        #pragma unroll
        for (int off = 1; off < 32; off <<= 1){
            unsigned v = __shfl_down_sync(0xFFFFFFFFu, inc, off);
            if (lane + off < 32) inc += v;
        }
        if (lane == 0) sh[8 + w] = inc;
        __syncthreads();
        unsigned upper = 0;
        #pragma unroll
        for (int ww = 1; ww < 8; ww++) if (ww > w) upper += sh[8 + ww];
        unsigned cge = inc + upper;
        unsigned cgt = cge - h;
        if (cgt < (unsigned)need && cge >= (unsigned)need){
            sh[0] = (unsigned)tid;
            sh[1] = (unsigned)need - cgt;
            sh[2] = (h == (unsigned)need - cgt) ? 1u : 0u;
        }
        __syncthreads();
        unsigned D = sh[0];
        need = (int)sh[1];
        unsigned done = sh[2];
        prefix |= ((unsigned long long)D) << shift;
        if (done) return prefix;
        #pragma unroll
        for (int e = 0; e < 4; e++)
            if (e < npt)
                act[e] = act[e] && (((kv[e] >> shift) & 255) == (unsigned long long)D);
        __syncthreads();
    }
    return prefix;
}

// ---------------- fused SVD + two-level top-k + memory gather ----------------
__global__ __launch_bounds__(256) void select_gather_kernel(const float* __restrict__ core,
                                                            const float* __restrict__ mem,
                                                            float* __restrict__ d_out, int out_size)
{
    __shared__ float rs[1024];
    __shared__ unsigned hist[256];
    __shared__ unsigned sh[16];
    __shared__ int ridx[32], cidx[32];
    __shared__ float gg0[32], gg1[32], fc0[32], fc1[32];
    __shared__ float suv[8];
    __shared__ int cnt;
    __shared__ float sfs[2][TOPK];
    __shared__ int   sfidx[2][TOPK];
    int tok = blockIdx.x, tid = threadIdx.x;
    if (tid == 0){
        float aux = 0.f;
        #pragma unroll
        for (int hh = 0; hh < 2; hh++){
            float u0,u1,t0,t1,ap;
            svd2x2(core, hh, u0, u1, t0, t1, ap);
            suv[hh*4+0]=u0; suv[hh*4+1]=u1; suv[hh*4+2]=t0; suv[hh*4+3]=t1;
            aux += ap;
        }
        if (tok == 0 && out_size > OUT_MAIN) d_out[OUT_MAIN] = aux*0.1f;
    }
    #pragma unroll
    for (int e = 0; e < 4; e++) rs[tid + e*256] = g_sc[(size_t)tok*1024 + tid + e*256];
    __syncthreads();

    for (int h = 0; h < 2; h++){
        float u0 = suv[h*4+0], u1 = suv[h*4+1];
        float t0 = suv[h*4+2], t1 = suv[h*4+3];
        float c00 = core[h*4+0], c01 = core[h*4+1], c10 = core[h*4+2], c11 = core[h*4+3];

        if (tid == 0) cnt = 0;
        unsigned long long kr = pack_key(rs[2*tid]*u0 + rs[2*tid+1]*u1, (unsigned)tid);
        unsigned long long T = radix_select32(&kr, 1, tid, hist, sh);
        if (kr >= T){ int s = atomicAdd(&cnt, 1); ridx[s] = tid; }
        __syncthreads();
        if (tid < 32){
            int mi = ridx[tid];
            float f0 = rs[2*mi], f1 = rs[2*mi+1];
            gg0[tid] = f0*c00 + f1*c10;
            gg1[tid] = f0*c01 + f1*c11;
        }

        if (tid == 0) cnt = 0;
        unsigned long long kc = pack_key(rs[512 + 2*tid]*t0 + rs[512 + 2*tid+1]*t1, (unsigned)tid);
        T = radix_select32(&kc, 1, tid, hist, sh);
        if (kc >= T){ int s = atomicAdd(&cnt, 1); cidx[s] = tid; }
        __syncthreads();
        if (tid < 32){
            int mi = cidx[tid];
            fc0[tid] = rs[512 + 2*mi];
            fc1[tid] = rs[512 + 2*mi+1];
        }
        __syncthreads();

        if (tid == 0) cnt = 0;
        unsigned long long kv[4];
        #pragma unroll
        for (int c = 0; c < 4; c++){
            int p = c*256 + tid;
            int i = p >> 5, j = p & 31;
            float val = gg0[i]*fc0[j] + gg1[i]*fc1[j];
            kv[c] = pack_key(val, (unsigned)p);
        }
        T = radix_select32(kv, 4, tid, hist, sh);
        #pragma unroll
        for (int c = 0; c < 4; c++){
            if (kv[c] >= T){
                int s = atomicAdd(&cnt, 1);
                int p = (int)(0xFFFFFFFFu - (unsigned)(kv[c] & 0xFFFFFFFFu));
                float val = unsortable_f((unsigned)(kv[c] >> 32));
                sfs[h][s]   = 1.f/(1.f + expf(-val));
                sfidx[h][s] = ridx[p >> 5]*NKEY + cidx[p & 31];
            }
        }
        __syncthreads();
    }

    // gather phase
    int h = tid >> 7, t = tid & 127;
    float4 acc = {0.f,0.f,0.f,0.f};
    #pragma unroll 16
    for (int k = 0; k < TOPK; k++){
        const float4* row = (const float4*)(mem + (size_t)sfidx[h][k]*DV);
        float4 v = __ldg(row + t);
        float ww = sfs[h][k];
        acc.x += ww*v.x; acc.y += ww*v.y; acc.z += ww*v.z; acc.w += ww*v.w;
    }
    ((float4*)(d_out + (size_t)tok*1024 + h*DV))[t] = acc;
}

extern "C" void kernel_launch(void* const* d_in, const int* in_sizes, int n_in,
                              void* d_out, int out_size)
{
    const float* tokens  = (const float*)d_in[0];
    const float* rms_w   = (const float*)d_in[1];
    const float* conv_w  = (const float*)d_in[2];
    const float* conv_b  = (const float*)d_in[3];
    const float* wq      = (const float*)d_in[4];
    const float* qln_w   = (const float*)d_in[5];
    const float* keys    = (const float*)d_in[6];
    const float* core    = (const float*)d_in[7];
    const float* mems    = (const float*)d_in[8];
    float* out = (float*)d_out;

    float* x2; cudaGetSymbolAddress((void**)&x2, g_x2);
    float* q;  cudaGetSymbolAddress((void**)&q, g_q);
    float* sc; cudaGetSymbolAddress((void**)&sc, g_sc);

    rms_kernel<<<TOK/2, 512>>>(tokens);
    conv_kernel<<<(TOK/4)*(DIM/4)/256, 256>>>(tokens, rms_w, conv_w, conv_b);
    gemm_q<<<dim3(1,32,8), 256>>>(x2, wq, q);
    ln_kernel<<<TOK/8, 256>>>(qln_w);
    gemm_sc<<<dim3(8,32,1), 256>>>(q, keys, sc);
    select_gather_kernel<<<TOK, 256>>>(core, mems, out, out_size);
}

// round 14
// speedup vs baseline: 1.4017x; 1.4017x over previous
#include <cuda_runtime.h>
#include <cuda_bf16.h>
#include <math.h>

#define BB 2
#define NN 1024
#define TOK (BB*NN)
#define DIM 1024
#define DQK 128
#define NKEY 256
#define TOPK 32
#define DV 512
#define KCONV 5
#define OUT_MAIN (TOK*1024)

__device__ float g_x2[TOK*DIM];
__device__ float g_qpart[8*TOK*DQK];
__device__ float g_sc[TOK*1024];

// gemm_sc dynamic smem: qst[128][68] + Bs[2][16][132]
#define QST_FLOATS (128*68)
#define BS_FLOATS  (2*16*132)
#define SMEM_SC ((QST_FLOATS + BS_FLOATS)*4)

__device__ __forceinline__ float fsign(float a, float b){ return (b >= 0.f) ? fabsf(a) : -fabsf(a); }
__device__ __forceinline__ unsigned sortable_f(float f){
    unsigned u = __float_as_uint(f);
    return (u & 0x80000000u) ? ~u : (u | 0x80000000u);
}
__device__ __forceinline__ float unsortable_f(unsigned s){
    unsigned u = (s & 0x80000000u) ? (s ^ 0x80000000u) : ~s;
    return __uint_as_float(u);
}
__device__ __forceinline__ unsigned long long pack_key(float v, unsigned idx){
    return (((unsigned long long)sortable_f(v)) << 32) | (unsigned long long)(0xFFFFFFFFu - idx);
}

// ---------------- LAPACK slasv2 port ----------------
__device__ void slasv2_dev(float f, float g, float h,
                           float& ssmin, float& ssmax,
                           float& snr, float& csr, float& snl, float& csl)
{
    float ft=f, fa=fabsf(f), ht=h, ha=fabsf(h);
    int pmax = 1;
    bool swp = (ha > fa);
    if (swp){ pmax = 3; float t; t=ft; ft=ht; ht=t; t=fa; fa=ha; ha=t; }
    float gt=g, ga=fabsf(g);
    float clt=0.f, crt=0.f, slt=0.f, srt=0.f;
    if (ga == 0.f){
        ssmin = ha; ssmax = fa; clt=1.f; crt=1.f; slt=0.f; srt=0.f;
    } else {
        bool gasmal = true;
        if (ga > fa){
            pmax = 2;
            if ((fa/ga) < 5.9604645e-08f){
                gasmal = false;
                ssmax = ga;
                ssmin = (ha > 1.f) ? (fa/(ga/ha)) : ((fa/ga)*ha);
                clt = 1.f; slt = ht/gt; srt = 1.f; crt = ft/gt;
            }
        }
        if (gasmal){
            float d_ = fa - ha;
            float l  = (d_ == fa) ? 1.f : d_/fa;
            float m  = gt/ft;
            float t  = 2.f - l;
            float mm = m*m, tt = t*t;
            float s  = sqrtf(tt + mm);
            float r_ = (l == 0.f) ? fabsf(m) : sqrtf(l*l + mm);
            float a_ = 0.5f*(s + r_);
            ssmin = ha/a_;
            ssmax = fa*a_;
            if (mm == 0.f){
                t = (l == 0.f) ? (fsign(2.f, ft)*fsign(1.f, gt))
                               : (gt/fsign(d_, ft) + m/t);
            } else {
                t = (m/(s + t) + m/(r_ + l))*(1.f + a_);
            }
            float l2 = sqrtf(t*t + 4.f);
            crt = 2.f/l2;
            srt = t/l2;
            clt = (crt + srt*m)/a_;
            slt = (ht/ft)*srt/a_;
        }
    }
    if (swp){ csl = srt; snl = crt; csr = slt; snr = clt; }
    else    { csl = clt; snl = slt; csr = crt; snr = srt; }
    float ts = 0.f;
    if (pmax == 1) ts = fsign(1.f, csr)*fsign(1.f, csl)*fsign(1.f, f);
    if (pmax == 2) ts = fsign(1.f, snr)*fsign(1.f, csl)*fsign(1.f, g);
    if (pmax == 3) ts = fsign(1.f, snr)*fsign(1.f, snl)*fsign(1.f, h);
    ssmax = fsign(ssmax, ts);
    ssmin = fsign(ssmin, ts*fsign(1.f, f)*fsign(1.f, h));
}

__device__ void svd2x2(const float* core, int hh, float& u0, float& u1,
                       float& t0, float& t1, float& auxp)
{
    float a = core[hh*4+0], b = core[hh*4+1];
    float c = core[hh*4+2], d = core[hh*4+3];
    float q00=1.f,q01=0.f,q10=0.f,q11=1.f;
    float d1, e1, d2;
    if (c != 0.f){
        float nrm  = sqrtf(a*a + c*c);
        float beta = (a >= 0.f) ? -nrm : nrm;
        float tau  = (beta - a)/beta;
        float v    = c/(a - beta);
        float w    = b + v*d;
        e1 = b - tau*w;
        d2 = d - tau*v*w;
        d1 = beta;
        q00 = 1.f - tau; q01 = -tau*v; q10 = -tau*v; q11 = 1.f - tau*v*v;
    } else { d1 = a; e1 = b; d2 = d; }
    float ssmin, ssmax, snr, csr, snl, csl;
    slasv2_dev(d1, e1, d2, ssmin, ssmax, snr, csr, snl, csl);
    float vt0 = csr, vt1 = snr;
    float s1 = ssmax;
    if (s1 < 0.f){ s1 = -s1; vt0 = -vt0; vt1 = -vt1; }
    float s2 = fabsf(ssmin);
    u0 = q00*csl + q01*snl;
    u1 = q10*csl + q11*snl;
    t0 = vt0;
    t1 = vt1;
    float r = s2 - 0.15f;
    auxp = (r > 0.f) ? r*r : 0.f;
}

// ---------------- fused RMSNorm + depthwise causal conv ----------------
// block = 256 thr = full 1024 dims (float4 each) of 4 consecutive tokens.
// Also computes invrms of the 8 involved tokens from its own loads.
__global__ __launch_bounds__(256) void conv_kernel(const float* __restrict__ tokens,
                            const float* __restrict__ rms_w,
                            const float* __restrict__ conv_w,
                            const float* __restrict__ conv_b)
{
    int tid = threadIdx.x;
    int grp = blockIdx.x;                 // 0..TOK/4-1
    int ng  = grp & (NN/4 - 1);
    int bb  = grp >> 8;
    int d   = tid*4;
    float4 rw = *(const float4*)(rms_w + d);
    float4 cb = *(const float4*)(conv_b + d);
    float wv[4][KCONV];
    #pragma unroll
    for (int dd = 0; dd < 4; dd++)
        #pragma unroll
        for (int k = 0; k < KCONV; k++) wv[dd][k] = conv_w[(d+dd)*KCONV + k];
    float4 xv[8];
    float pp[8];
    #pragma unroll
    for (int j = 0; j < 8; j++){
        int nn = ng*4 - 4 + j;
        if (nn >= 0){
            int t2 = (bb << 10) + nn;
            xv[j] = *(const float4*)(tokens + (size_t)t2*DIM + d);
            pp[j] = xv[j].x*xv[j].x + xv[j].y*xv[j].y + xv[j].z*xv[j].z + xv[j].w*xv[j].w;
        } else { xv[j] = make_float4(0.f,0.f,0.f,0.f); pp[j] = 0.f; }
    }
    // block-reduce the 8 per-token sums of squares
    #pragma unroll
    for (int j = 0; j < 8; j++)
        #pragma unroll
        for (int o = 16; o; o >>= 1) pp[j] += __shfl_xor_sync(0xFFFFFFFFu, pp[j], o);
    __shared__ float red[8][8];
    __shared__ float inv_sh[8];
    int w = tid >> 5, l = tid & 31;
    if (l == 0)
        #pragma unroll
        for (int j = 0; j < 8; j++) red[w][j] = pp[j];
    __syncthreads();
    if (tid < 8){
        float s = 0.f;
        #pragma unroll
        for (int ww = 0; ww < 8; ww++) s += red[ww][tid];
        inv_sh[tid] = rsqrtf(s*(1.f/1024.f) + 1.1920929e-07f);
    }
    __syncthreads();
    #pragma unroll
    for (int j = 0; j < 8; j++){
        float ir = inv_sh[j];
        xv[j].x *= ir*rw.x; xv[j].y *= ir*rw.y; xv[j].z *= ir*rw.z; xv[j].w *= ir*rw.w;
    }
    #pragma unroll
    for (int i = 0; i < 4; i++){
        float4 acc = cb;
        #pragma unroll
        for (int k = 0; k < KCONV; k++){
            acc.x += wv[0][k]*xv[i+k].x;
            acc.y += wv[1][k]*xv[i+k].y;
            acc.z += wv[2][k]*xv[i+k].z;
            acc.w += wv[3][k]*xv[i+k].w;
        }
        *(float4*)(g_x2 + (size_t)((bb << 10) + ng*4 + i)*DIM + d) = acc;
    }
}

// GEMM1: qpart[z] = x2 @ wq^T, split-K=8.  Tile M64 x N128, 256 thr, 8x4 acc.
__global__ __launch_bounds__(256) void gemm_q(const float* __restrict__ A,
                                              const float* __restrict__ B,
                                              float* __restrict__ C)
{
    __shared__ float As[2][16][68];
    __shared__ float Bs[2][16][132];
    int tid = threadIdx.x, tx = tid & 31, ty = tid >> 5;
    int m0 = blockIdx.y*64, k0 = blockIdx.z*128;
    C += (size_t)blockIdx.z*(TOK*DQK);
    const float* Ab = A + (size_t)m0*DIM + k0;
    const float* Bb = B + k0;
    float acc[8][4];
    #pragma unroll
    for (int i = 0; i < 8; i++)
        #pragma unroll
        for (int j = 0; j < 4; j++) acc[i][j] = 0.f;
    float ra[4], rb[8];
    #pragma unroll
    for (int e = 0; e < 4; e++){ int f = tid + e*256; ra[e] = Ab[(size_t)(f >> 4)*DIM + (f & 15)]; }
    #pragma unroll
    for (int e = 0; e < 8; e++){ int f = tid + e*256; rb[e] = Bb[(size_t)(f >> 4)*DIM + (f & 15)]; }
    #pragma unroll
    for (int e = 0; e < 4; e++){ int f = tid + e*256; As[0][f & 15][f >> 4] = ra[e]; }
    #pragma unroll
    for (int e = 0; e < 8; e++){ int f = tid + e*256; Bs[0][f & 15][f >> 4] = rb[e]; }
    __syncthreads();
    int cur = 0;
    for (int kk = 0; kk < 128; kk += 16){
        bool nxt = (kk + 16) < 128;
        if (nxt){
            #pragma unroll
            for (int e = 0; e < 4; e++){ int f = tid + e*256; ra[e] = Ab[(size_t)(f >> 4)*DIM + kk + 16 + (f & 15)]; }
            #pragma unroll
            for (int e = 0; e < 8; e++){ int f = tid + e*256; rb[e] = Bb[(size_t)(f >> 4)*DIM + kk + 16 + (f & 15)]; }
        }
        #pragma unroll
        for (int k = 0; k < 16; k++){
            float4 a0 = *(const float4*)&As[cur][k][ty*8];
            float4 a1 = *(const float4*)&As[cur][k][ty*8+4];
            float4 b0 = *(const float4*)&Bs[cur][k][tx*4];
            float a[8] = {a0.x,a0.y,a0.z,a0.w,a1.x,a1.y,a1.z,a1.w};
            float b[4] = {b0.x,b0.y,b0.z,b0.w};
            #pragma unroll
            for (int i = 0; i < 8; i++)
                #pragma unroll
                for (int j = 0; j < 4; j++)
                    acc[i][j] += a[i]*b[j];
        }
        if (nxt){
            #pragma unroll
            for (int e = 0; e < 4; e++){ int f = tid + e*256; As[cur^1][f & 15][f >> 4] = ra[e]; }
            #pragma unroll
            for (int e = 0; e < 8; e++){ int f = tid + e*256; Bs[cur^1][f & 15][f >> 4] = rb[e]; }
            __syncthreads();
            cur ^= 1;
        }
    }
    #pragma unroll
    for (int i = 0; i < 8; i++){
        float4 v = {acc[i][0], acc[i][1], acc[i][2], acc[i][3]};
        *(float4*)(C + (size_t)(m0 + ty*8 + i)*DQK + tx*4) = v;
    }
}

// GEMM2 with fused split-K reduce + LayerNorm prologue (A kept in smem) and
// fused keys permutation on the B path.  Tile M64 x N128, 8x4 acc.
__global__ __launch_bounds__(256) void gemm_sc(const float* __restrict__ qln_w,
                                               const float* __restrict__ keys,
                                               float* __restrict__ C)
{
    extern __shared__ float smem[];
    float (*qst)[68] = (float(*)[68])smem;          // [k 0..127][m 0..63 +pad]
    float* BsB = smem + QST_FLOATS;                  // Bs[2][16][132]
#define BS(buf,k,n) BsB[(((buf)*16 + (k))*132) + (n)]
    int tid = threadIdx.x, tx = tid & 31, ty = tid >> 5;
    int m0 = blockIdx.y*64, n0 = blockIdx.x*128;
    unsigned brow[8];
    #pragma unroll
    for (int e = 0; e < 8; e++){
        int f = tid + e*256;
        int j = n0 + (f >> 4);
        int c = j >> 9, rem = j & 511, m = rem >> 1, r = rem & 1;
        brow[e] = (unsigned)(((c*2 + r)*NKEY + m))*DQK;
    }
    // issue first B tile loads early
    float rb[8];
    #pragma unroll
    for (int e = 0; e < 8; e++){ int f = tid + e*256; rb[e] = keys[brow[e] + (f & 15)]; }

    // ---- prologue: split-K sum + LayerNorm for rows m0..m0+63 ----
    {
        int r  = tid >> 2;          // local row 0..63
        int cg = tid & 3;           // column group: 32 cols each
        int row = m0 + r;
        float4 q4[8];
        #pragma unroll
        for (int c4 = 0; c4 < 8; c4++){
            int col = cg*32 + c4*4;
            float4 v = make_float4(0.f,0.f,0.f,0.f);
            #pragma unroll
            for (int z = 0; z < 8; z++){
                float4 p = *(const float4*)(g_qpart + (size_t)z*TOK*DQK + (size_t)row*DQK + col);
                v.x += p.x; v.y += p.y; v.z += p.z; v.w += p.w;
            }
            q4[c4] = v;
        }
        float s = 0.f;
        #pragma unroll
        for (int c4 = 0; c4 < 8; c4++) s += q4[c4].x + q4[c4].y + q4[c4].z + q4[c4].w;
        s += __shfl_xor_sync(0xFFFFFFFFu, s, 1);
        s += __shfl_xor_sync(0xFFFFFFFFu, s, 2);
        float mu = s * (1.f/128.f);
        float s2 = 0.f;
        #pragma unroll
        for (int c4 = 0; c4 < 8; c4++){
            q4[c4].x -= mu; q4[c4].y -= mu; q4[c4].z -= mu; q4[c4].w -= mu;
            s2 += q4[c4].x*q4[c4].x + q4[c4].y*q4[c4].y + q4[c4].z*q4[c4].z + q4[c4].w*q4[c4].w;
        }
        s2 += __shfl_xor_sync(0xFFFFFFFFu, s2, 1);
        s2 += __shfl_xor_sync(0xFFFFFFFFu, s2, 2);
        float inv = rsqrtf(s2*(1.f/128.f) + 1e-5f);
        #pragma unroll
        for (int c4 = 0; c4 < 8; c4++){
            int col = cg*32 + c4*4;
            float4 qw = *(const float4*)(qln_w + col);
            qst[col+0][r] = q4[c4].x*inv*qw.x;
            qst[col+1][r] = q4[c4].y*inv*qw.y;
            qst[col+2][r] = q4[c4].z*inv*qw.z;
            qst[col+3][r] = q4[c4].w*inv*qw.w;
        }
    }
    // store first B tile
    #pragma unroll
    for (int e = 0; e < 8; e++){ int f = tid + e*256; BS(0, f & 15, f >> 4) = rb[e]; }
    __syncthreads();

    float acc[8][4];
    #pragma unroll
    for (int i = 0; i < 8; i++)
        #pragma unroll
        for (int j = 0; j < 4; j++) acc[i][j] = 0.f;
    int cur = 0;
    for (int kk = 0; kk < 128; kk += 16){
        bool nxt = (kk + 16) < 128;
        if (nxt){
            #pragma unroll
            for (int e = 0; e < 8; e++){ int f = tid + e*256; rb[e] = keys[brow[e] + kk + 16 + (f & 15)]; }
        }
        #pragma unroll
        for (int k = 0; k < 16; k++){
            float4 a0 = *(const float4*)&qst[kk + k][ty*8];
            float4 a1 = *(const float4*)&qst[kk + k][ty*8+4];
            float4 b0 = *(const float4*)&BS(cur, k, tx*4);
            float a[8] = {a0.x,a0.y,a0.z,a0.w,a1.x,a1.y,a1.z,a1.w};
            float b[4] = {b0.x,b0.y,b0.z,b0.w};
            #pragma unroll
            for (int i = 0; i < 8; i++)
                #pragma unroll
                for (int j = 0; j < 4; j++)
                    acc[i][j] += a[i]*b[j];
        }
        if (nxt){
            #pragma unroll
            for (int e = 0; e < 8; e++){ int f = tid + e*256; BS(cur^1, f & 15, f >> 4) = rb[e]; }
            __syncthreads();
            cur ^= 1;
        }
    }
    #pragma unroll
    for (int i = 0; i < 8; i++){
        float4 v = {acc[i][0], acc[i][1], acc[i][2], acc[i][3]};
        *(float4*)(C + (size_t)(m0 + ty*8 + i)*1024 + n0 + tx*4) = v;
    }
#undef BS
}

// ---------------- block-wide exact top-32 threshold via MSB radix descent ----------------
__device__ unsigned long long radix_select32(const unsigned long long* kv, int npt, int tid,
                                             unsigned* hist, unsigned* sh)
{
    unsigned long long prefix = 0;
    bool act[4] = {true, true, true, true};
    int need = 32;
    int lane = tid & 31, w = tid >> 5;
    for (int shift = 56; shift >= 0; shift -= 8){
        hist[tid] = 0;
        __syncthreads();
        #pragma unroll
        for (int e = 0; e < 4; e++)
            if (e < npt && act[e])
                atomicAdd(&hist[(unsigned)((kv[e] >> shift) & 255)], 1u);
        __syncthreads();
        unsigned h = hist[tid];
        unsigned inc = h;
        #pragma unroll
        for (int off = 1; off < 32; off <<= 1){
            unsigned v = __shfl_down_sync(0xFFFFFFFFu, inc, off);
            if (lane + off < 32) inc += v;
        }
        if (lane == 0) sh[8 + w] = inc;
        __syncthreads();
        unsigned upper = 0;
        #pragma unroll
        for (int ww = 1; ww < 8; ww++) if (ww > w) upper += sh[8 + ww];
        unsigned cge = inc + upper;
        unsigned cgt = cge - h;
        if (cgt < (unsigned)need && cge >= (unsigned)need){
            sh[0] = (unsigned)tid;
            sh[1] = (unsigned)need - cgt;
            sh[2] = (h == (unsigned)need - cgt) ? 1u : 0u;
        }
        __syncthreads();
        unsigned D = sh[0];
        need = (int)sh[1];
        unsigned done = sh[2];
        prefix |= ((unsigned long long)D) << shift;
        if (done) return prefix;
        #pragma unroll
        for (int e = 0; e < 4; e++)
            if (e < npt)
                act[e] = act[e] && (((kv[e] >> shift) & 255) == (unsigned long long)D);
        __syncthreads();
    }
    return prefix;
}

// ---------------- fused SVD + two-level top-k + memory gather ----------------
__global__ __launch_bounds__(256) void select_gather_kernel(const float* __restrict__ core,
                                                            const float* __restrict__ mem,
                                                            float* __restrict__ d_out, int out_size)
{
    __shared__ float rs[1024];
    __shared__ unsigned hist[256];
    __shared__ unsigned sh[16];
    __shared__ int ridx[32], cidx[32];
    __shared__ float gg0[32], gg1[32], fc0[32], fc1[32];
    __shared__ float suv[8];
    __shared__ int cnt;
    __shared__ float sfs[2][TOPK];
    __shared__ int   sfidx[2][TOPK];
    int tok = blockIdx.x, tid = threadIdx.x;
    if (tid == 0){
        float aux = 0.f;
        #pragma unroll
        for (int hh = 0; hh < 2; hh++){
            float u0,u1,t0,t1,ap;
            svd2x2(core, hh, u0, u1, t0, t1, ap);
            suv[hh*4+0]=u0; suv[hh*4+1]=u1; suv[hh*4+2]=t0; suv[hh*4+3]=t1;
            aux += ap;
        }
        if (tok == 0 && out_size > OUT_MAIN) d_out[OUT_MAIN] = aux*0.1f;
    }
    #pragma unroll
    for (int e = 0; e < 4; e++) rs[tid + e*256] = g_sc[(size_t)tok*1024 + tid + e*256];
    __syncthreads();

    for (int h = 0; h < 2; h++){
        float u0 = suv[h*4+0], u1 = suv[h*4+1];
        float t0 = suv[h*4+2], t1 = suv[h*4+3];
        float c00 = core[h*4+0], c01 = core[h*4+1], c10 = core[h*4+2], c11 = core[h*4+3];

        if (tid == 0) cnt = 0;
        unsigned long long kr = pack_key(rs[2*tid]*u0 + rs[2*tid+1]*u1, (unsigned)tid);
        unsigned long long T = radix_select32(&kr, 1, tid, hist, sh);
        if (kr >= T){ int s = atomicAdd(&cnt, 1); ridx[s] = tid; }
        __syncthreads();
        if (tid < 32){
            int mi = ridx[tid];
            float f0 = rs[2*mi], f1 = rs[2*mi+1];
            gg0[tid] = f0*c00 + f1*c10;
            gg1[tid] = f0*c01 + f1*c11;
        }

        if (tid == 0) cnt = 0;
        unsigned long long kc = pack_key(rs[512 + 2*tid]*t0 + rs[512 + 2*tid+1]*t1, (unsigned)tid);
        T = radix_select32(&kc, 1, tid, hist, sh);
        if (kc >= T){ int s = atomicAdd(&cnt, 1); cidx[s] = tid; }
        __syncthreads();
        if (tid < 32){
            int mi = cidx[tid];
            fc0[tid] = rs[512 + 2*mi];
            fc1[tid] = rs[512 + 2*mi+1];
        }
        __syncthreads();

        if (tid == 0) cnt = 0;
        unsigned long long kv[4];
        #pragma unroll
        for (int c = 0; c < 4; c++){
            int p = c*256 + tid;
            int i = p >> 5, j = p & 31;
            float val = gg0[i]*fc0[j] + gg1[i]*fc1[j];
            kv[c] = pack_key(val, (unsigned)p);
        }
        T = radix_select32(kv, 4, tid, hist, sh);
        #pragma unroll
        for (int c = 0; c < 4; c++){
            if (kv[c] >= T){
                int s = atomicAdd(&cnt, 1);
                int p = (int)(0xFFFFFFFFu - (unsigned)(kv[c] & 0xFFFFFFFFu));
                float val = unsortable_f((unsigned)(kv[c] >> 32));
                sfs[h][s]   = 1.f/(1.f + expf(-val));
                sfidx[h][s] = ridx[p >> 5]*NKEY + cidx[p & 31];
            }
        }
        __syncthreads();
    }

    // gather phase
    int h = tid >> 7, t = tid & 127;
    float4 acc = {0.f,0.f,0.f,0.f};
    #pragma unroll 8
    for (int k = 0; k < TOPK; k++){
        const float4* row = (const float4*)(mem + (size_t)sfidx[h][k]*DV);
        float4 v = __ldg(row + t);
        float ww = sfs[h][k];
        acc.x += ww*v.x; acc.y += ww*v.y; acc.z += ww*v.z; acc.w += ww*v.w;
    }
    ((float4*)(d_out + (size_t)tok*1024 + h*DV))[t] = acc;
}

extern "C" void kernel_launch(void* const* d_in, const int* in_sizes, int n_in,
                              void* d_out, int out_size)
{
    const float* tokens  = (const float*)d_in[0];
    const float* rms_w   = (const float*)d_in[1];
    const float* conv_w  = (const float*)d_in[2];
    const float* conv_b  = (const float*)d_in[3];
    const float* wq      = (const float*)d_in[4];
    const float* qln_w   = (const float*)d_in[5];
    const float* keys    = (const float*)d_in[6];
    const float* core    = (const float*)d_in[7];
    const float* mems    = (const float*)d_in[8];
    float* out = (float*)d_out;

    float* x2;    cudaGetSymbolAddress((void**)&x2, g_x2);
    float* qpart; cudaGetSymbolAddress((void**)&qpart, g_qpart);
    float* sc;    cudaGetSymbolAddress((void**)&sc, g_sc);

    static int smem_set = 0;
    if (!smem_set){
        cudaFuncSetAttribute(gemm_sc, cudaFuncAttributeMaxDynamicSharedMemorySize, SMEM_SC);
        smem_set = 1;
    }

    conv_kernel<<<TOK/4, 256>>>(tokens, rms_w, conv_w, conv_b);
    gemm_q<<<dim3(1,32,8), 256>>>(x2, wq, qpart);
    gemm_sc<<<dim3(8,32,1), 256, SMEM_SC>>>(qln_w, keys, sc);
    select_gather_kernel<<<TOK, 256>>>(core, mems, out, out_size);
}

// round 15
// speedup vs baseline: 1.5970x; 1.1393x over previous
#include <cuda_runtime.h>
#include <cuda_bf16.h>
#include <math.h>

#define BB 2
#define NN 1024
#define TOK (BB*NN)
#define DIM 1024
#define DQK 128
#define NKEY 256
#define TOPK 32
#define DV 512
#define KCONV 5
#define OUT_MAIN (TOK*1024)

__device__ float g_x2[TOK*DIM];
__device__ float g_qpart[8*TOK*DQK];
__device__ float g_q[TOK*DQK];
__device__ float g_sc[TOK*1024];

__device__ __forceinline__ float fsign(float a, float b){ return (b >= 0.f) ? fabsf(a) : -fabsf(a); }
__device__ __forceinline__ unsigned sortable_f(float f){
    unsigned u = __float_as_uint(f);
    return (u & 0x80000000u) ? ~u : (u | 0x80000000u);
}
__device__ __forceinline__ float unsortable_f(unsigned s){
    unsigned u = (s & 0x80000000u) ? (s ^ 0x80000000u) : ~s;
    return __uint_as_float(u);
}
__device__ __forceinline__ unsigned long long pack_key(float v, unsigned idx){
    return (((unsigned long long)sortable_f(v)) << 32) | (unsigned long long)(0xFFFFFFFFu - idx);
}

// ---------------- LAPACK slasv2 port ----------------
__device__ void slasv2_dev(float f, float g, float h,
                           float& ssmin, float& ssmax,
                           float& snr, float& csr, float& snl, float& csl)
{
    float ft=f, fa=fabsf(f), ht=h, ha=fabsf(h);
    int pmax = 1;
    bool swp = (ha > fa);
    if (swp){ pmax = 3; float t; t=ft; ft=ht; ht=t; t=fa; fa=ha; ha=t; }
    float gt=g, ga=fabsf(g);
    float clt=0.f, crt=0.f, slt=0.f, srt=0.f;
    if (ga == 0.f){
        ssmin = ha; ssmax = fa; clt=1.f; crt=1.f; slt=0.f; srt=0.f;
    } else {
        bool gasmal = true;
        if (ga > fa){
            pmax = 2;
            if ((fa/ga) < 5.9604645e-08f){
                gasmal = false;
                ssmax = ga;
                ssmin = (ha > 1.f) ? (fa/(ga/ha)) : ((fa/ga)*ha);
                clt = 1.f; slt = ht/gt; srt = 1.f; crt = ft/gt;
            }
        }
        if (gasmal){
            float d_ = fa - ha;
            float l  = (d_ == fa) ? 1.f : d_/fa;
            float m  = gt/ft;
            float t  = 2.f - l;
            float mm = m*m, tt = t*t;
            float s  = sqrtf(tt + mm);
            float r_ = (l == 0.f) ? fabsf(m) : sqrtf(l*l + mm);
            float a_ = 0.5f*(s + r_);
            ssmin = ha/a_;
            ssmax = fa*a_;
            if (mm == 0.f){
                t = (l == 0.f) ? (fsign(2.f, ft)*fsign(1.f, gt))
                               : (gt/fsign(d_, ft) + m/t);
            } else {
                t = (m/(s + t) + m/(r_ + l))*(1.f + a_);
            }
            float l2 = sqrtf(t*t + 4.f);
            crt = 2.f/l2;
            srt = t/l2;
            clt = (crt + srt*m)/a_;
            slt = (ht/ft)*srt/a_;
        }
    }
    if (swp){ csl = srt; snl = crt; csr = slt; snr = clt; }
    else    { csl = clt; snl = slt; csr = crt; snr = srt; }
    float ts = 0.f;
    if (pmax == 1) ts = fsign(1.f, csr)*fsign(1.f, csl)*fsign(1.f, f);
    if (pmax == 2) ts = fsign(1.f, snr)*fsign(1.f, csl)*fsign(1.f, g);
    if (pmax == 3) ts = fsign(1.f, snr)*fsign(1.f, snl)*fsign(1.f, h);
    ssmax = fsign(ssmax, ts);
    ssmin = fsign(ssmin, ts*fsign(1.f, f)*fsign(1.f, h));
}

__device__ void svd2x2(const float* core, int hh, float& u0, float& u1,
                       float& t0, float& t1, float& auxp)
{
    float a = core[hh*4+0], b = core[hh*4+1];
    float c = core[hh*4+2], d = core[hh*4+3];
    float q00=1.f,q01=0.f,q10=0.f,q11=1.f;
    float d1, e1, d2;
    if (c != 0.f){
        float nrm  = sqrtf(a*a + c*c);
        float beta = (a >= 0.f) ? -nrm : nrm;
        float tau  = (beta - a)/beta;
        float v    = c/(a - beta);
        float w    = b + v*d;
        e1 = b - tau*w;
        d2 = d - tau*v*w;
        d1 = beta;
        q00 = 1.f - tau; q01 = -tau*v; q10 = -tau*v; q11 = 1.f - tau*v*v;
    } else { d1 = a; e1 = b; d2 = d; }
    float ssmin, ssmax, snr, csr, snl, csl;
    slasv2_dev(d1, e1, d2, ssmin, ssmax, snr, csr, snl, csl);
    float vt0 = csr, vt1 = snr;
    float s1 = ssmax;
    if (s1 < 0.f){ s1 = -s1; vt0 = -vt0; vt1 = -vt1; }
    float s2 = fabsf(ssmin);
    u0 = q00*csl + q01*snl;
    u1 = q10*csl + q11*snl;
    t0 = vt0;
    t1 = vt1;
    float r = s2 - 0.15f;
    auxp = (r > 0.f) ? r*r : 0.f;
}

// ---------------- fused RMSNorm + depthwise causal conv (validated R14) ----------------
__global__ __launch_bounds__(256) void conv_kernel(const float* __restrict__ tokens,
                            const float* __restrict__ rms_w,
                            const float* __restrict__ conv_w,
                            const float* __restrict__ conv_b)
{
    int tid = threadIdx.x;
    int grp = blockIdx.x;
    int ng  = grp & (NN/4 - 1);
    int bb  = grp >> 8;
    int d   = tid*4;
    float4 rw = *(const float4*)(rms_w + d);
    float4 cb = *(const float4*)(conv_b + d);
    float wv[4][KCONV];
    #pragma unroll
    for (int dd = 0; dd < 4; dd++)
        #pragma unroll
        for (int k = 0; k < KCONV; k++) wv[dd][k] = conv_w[(d+dd)*KCONV + k];
    float4 xv[8];
    float pp[8];
    #pragma unroll
    for (int j = 0; j < 8; j++){
        int nn = ng*4 - 4 + j;
        if (nn >= 0){
            int t2 = (bb << 10) + nn;
            xv[j] = *(const float4*)(tokens + (size_t)t2*DIM + d);
            pp[j] = xv[j].x*xv[j].x + xv[j].y*xv[j].y + xv[j].z*xv[j].z + xv[j].w*xv[j].w;
        } else { xv[j] = make_float4(0.f,0.f,0.f,0.f); pp[j] = 0.f; }
    }
    #pragma unroll
    for (int j = 0; j < 8; j++)
        #pragma unroll
        for (int o = 16; o; o >>= 1) pp[j] += __shfl_xor_sync(0xFFFFFFFFu, pp[j], o);
    __shared__ float red[8][8];
    __shared__ float inv_sh[8];
    int w = tid >> 5, l = tid & 31;
    if (l == 0)
        #pragma unroll
        for (int j = 0; j < 8; j++) red[w][j] = pp[j];
    __syncthreads();
    if (tid < 8){
        float s = 0.f;
        #pragma unroll
        for (int ww = 0; ww < 8; ww++) s += red[ww][tid];
        inv_sh[tid] = rsqrtf(s*(1.f/1024.f) + 1.1920929e-07f);
    }
    __syncthreads();
    #pragma unroll
    for (int j = 0; j < 8; j++){
        float ir = inv_sh[j];
        xv[j].x *= ir*rw.x; xv[j].y *= ir*rw.y; xv[j].z *= ir*rw.z; xv[j].w *= ir*rw.w;
    }
    #pragma unroll
    for (int i = 0; i < 4; i++){
        float4 acc = cb;
        #pragma unroll
        for (int k = 0; k < KCONV; k++){
            acc.x += wv[0][k]*xv[i+k].x;
            acc.y += wv[1][k]*xv[i+k].y;
            acc.z += wv[2][k]*xv[i+k].z;
            acc.w += wv[3][k]*xv[i+k].w;
        }
        *(float4*)(g_x2 + (size_t)((bb << 10) + ng*4 + i)*DIM + d) = acc;
    }
}

// GEMM1: qpart[z] = x2 @ wq^T, split-K=8.  Tile M64 x N128, 256 thr, 8x4 acc.
__global__ __launch_bounds__(256) void gemm_q(const float* __restrict__ A,
                                              const float* __restrict__ B,
                                              float* __restrict__ C)
{
    __shared__ float As[2][16][68];
    __shared__ float Bs[2][16][132];
    int tid = threadIdx.x, tx = tid & 31, ty = tid >> 5;
    int m0 = blockIdx.y*64, k0 = blockIdx.z*128;
    C += (size_t)blockIdx.z*(TOK*DQK);
    const float* Ab = A + (size_t)m0*DIM + k0;
    const float* Bb = B + k0;
    float acc[8][4];
    #pragma unroll
    for (int i = 0; i < 8; i++)
        #pragma unroll
        for (int j = 0; j < 4; j++) acc[i][j] = 0.f;
    float ra[4], rb[8];
    #pragma unroll
    for (int e = 0; e < 4; e++){ int f = tid + e*256; ra[e] = Ab[(size_t)(f >> 4)*DIM + (f & 15)]; }
    #pragma unroll
    for (int e = 0; e < 8; e++){ int f = tid + e*256; rb[e] = Bb[(size_t)(f >> 4)*DIM + (f & 15)]; }
    #pragma unroll
    for (int e = 0; e < 4; e++){ int f = tid + e*256; As[0][f & 15][f >> 4] = ra[e]; }
    #pragma unroll
    for (int e = 0; e < 8; e++){ int f = tid + e*256; Bs[0][f & 15][f >> 4] = rb[e]; }
    __syncthreads();
    int cur = 0;
    for (int kk = 0; kk < 128; kk += 16){
        bool nxt = (kk + 16) < 128;
        if (nxt){
            #pragma unroll
            for (int e = 0; e < 4; e++){ int f = tid + e*256; ra[e] = Ab[(size_t)(f >> 4)*DIM + kk + 16 + (f & 15)]; }
            #pragma unroll
            for (int e = 0; e < 8; e++){ int f = tid + e*256; rb[e] = Bb[(size_t)(f >> 4)*DIM + kk + 16 + (f & 15)]; }
        }
        #pragma unroll
        for (int k = 0; k < 16; k++){
            float4 a0 = *(const float4*)&As[cur][k][ty*8];
            float4 a1 = *(const float4*)&As[cur][k][ty*8+4];
            float4 b0 = *(const float4*)&Bs[cur][k][tx*4];
            float a[8] = {a0.x,a0.y,a0.z,a0.w,a1.x,a1.y,a1.z,a1.w};
            float b[4] = {b0.x,b0.y,b0.z,b0.w};
            #pragma unroll
            for (int i = 0; i < 8; i++)
                #pragma unroll
                for (int j = 0; j < 4; j++)
                    acc[i][j] += a[i]*b[j];
        }
        if (nxt){
            #pragma unroll
            for (int e = 0; e < 4; e++){ int f = tid + e*256; As[cur^1][f & 15][f >> 4] = ra[e]; }
            #pragma unroll
            for (int e = 0; e < 8; e++){ int f = tid + e*256; Bs[cur^1][f & 15][f >> 4] = rb[e]; }
            __syncthreads();
            cur ^= 1;
        }
    }
    #pragma unroll
    for (int i = 0; i < 8; i++){
        float4 v = {acc[i][0], acc[i][1], acc[i][2], acc[i][3]};
        *(float4*)(C + (size_t)(m0 + ty*8 + i)*DQK + tx*4) = v;
    }
}

// ln: warp-per-token, sums split-K partials, LN, writes g_q
__global__ void ln_kernel(const float* __restrict__ qln_w)
{
    int w = threadIdx.x >> 5, l = threadIdx.x & 31;
    int tok = blockIdx.x*8 + w;
    int col = l*4;
    float4 v = make_float4(0.f,0.f,0.f,0.f);
    #pragma unroll
    for (int z = 0; z < 8; z++){
        float4 p = *(const float4*)(g_qpart + (size_t)z*TOK*DQK + (size_t)tok*DQK + col);
        v.x += p.x; v.y += p.y; v.z += p.z; v.w += p.w;
    }
    float s = v.x + v.y + v.z + v.w;
    #pragma unroll
    for (int o = 16; o; o >>= 1) s += __shfl_xor_sync(0xFFFFFFFFu, s, o);
    float mu = s * (1.f/128.f);
    float4 dv = {v.x-mu, v.y-mu, v.z-mu, v.w-mu};
    float s2 = dv.x*dv.x + dv.y*dv.y + dv.z*dv.z + dv.w*dv.w;
    #pragma unroll
    for (int o = 16; o; o >>= 1) s2 += __shfl_xor_sync(0xFFFFFFFFu, s2, o);
    float inv = rsqrtf(s2*(1.f/128.f) + 1e-5f);
    float4 qw = *(const float4*)(qln_w + col);
    float4 r = {dv.x*inv*qw.x, dv.y*inv*qw.y, dv.z*inv*qw.z, dv.w*inv*qw.w};
    *(float4*)(g_q + (size_t)tok*DQK + col) = r;
}

// GEMM2: sc = q @ kp^T with fused keys permutation.  Tile M64 x N128, 8x4 acc.
__global__ __launch_bounds__(256) void gemm_sc(const float* __restrict__ A,
                                               const float* __restrict__ keys,
                                               float* __restrict__ C)
{
    __shared__ float As[2][16][68];
    __shared__ float Bs[2][16][132];
    int tid = threadIdx.x, tx = tid & 31, ty = tid >> 5;
    int m0 = blockIdx.y*64, n0 = blockIdx.x*128;
    const float* Ab = A + (size_t)m0*DQK;
    unsigned brow[8];
    #pragma unroll
    for (int e = 0; e < 8; e++){
        int f = tid + e*256;
        int j = n0 + (f >> 4);
        int c = j >> 9, rem = j & 511, m = rem >> 1, r = rem & 1;
        brow[e] = (unsigned)(((c*2 + r)*NKEY + m))*DQK;
    }
    float acc[8][4];
    #pragma unroll
    for (int i = 0; i < 8; i++)
        #pragma unroll
        for (int j = 0; j < 4; j++) acc[i][j] = 0.f;
    float ra[4], rb[8];
    #pragma unroll
    for (int e = 0; e < 4; e++){ int f = tid + e*256; ra[e] = Ab[(size_t)(f >> 4)*DQK + (f & 15)]; }
    #pragma unroll
    for (int e = 0; e < 8; e++){ int f = tid + e*256; rb[e] = keys[brow[e] + (f & 15)]; }
    #pragma unroll
    for (int e = 0; e < 4; e++){ int f = tid + e*256; As[0][f & 15][f >> 4] = ra[e]; }
    #pragma unroll
    for (int e = 0; e < 8; e++){ int f = tid + e*256; Bs[0][f & 15][f >> 4] = rb[e]; }
    __syncthreads();
    int cur = 0;
    for (int kk = 0; kk < 128; kk += 16){
        bool nxt = (kk + 16) < 128;
        if (nxt){
            #pragma unroll
            for (int e = 0; e < 4; e++){ int f = tid + e*256; ra[e] = Ab[(size_t)(f >> 4)*DQK + kk + 16 + (f & 15)]; }
            #pragma unroll
            for (int e = 0; e < 8; e++){ int f = tid + e*256; rb[e] = keys[brow[e] + kk + 16 + (f & 15)]; }
        }
        #pragma unroll
        for (int k = 0; k < 16; k++){
            float4 a0 = *(const float4*)&As[cur][k][ty*8];
            float4 a1 = *(const float4*)&As[cur][k][ty*8+4];
            float4 b0 = *(const float4*)&Bs[cur][k][tx*4];
            float a[8] = {a0.x,a0.y,a0.z,a0.w,a1.x,a1.y,a1.z,a1.w};
            float b[4] = {b0.x,b0.y,b0.z,b0.w};
            #pragma unroll
            for (int i = 0; i < 8; i++)
                #pragma unroll
                for (int j = 0; j < 4; j++)
                    acc[i][j] += a[i]*b[j];
        }
        if (nxt){
            #pragma unroll
            for (int e = 0; e < 4; e++){ int f = tid + e*256; As[cur^1][f & 15][f >> 4] = ra[e]; }
            #pragma unroll
            for (int e = 0; e < 8; e++){ int f = tid + e*256; Bs[cur^1][f & 15][f >> 4] = rb[e]; }
            __syncthreads();
            cur ^= 1;
        }
    }
    #pragma unroll
    for (int i = 0; i < 8; i++){
        float4 v = {acc[i][0], acc[i][1], acc[i][2], acc[i][3]};
        *(float4*)(C + (size_t)(m0 + ty*8 + i)*1024 + n0 + tx*4) = v;
    }
}

// ---------------- block-wide exact top-32 threshold via MSB radix descent ----------------
__device__ unsigned long long radix_select32(const unsigned long long* kv, int npt, int tid,
                                             unsigned* hist, unsigned* sh)
{
    unsigned long long prefix = 0;
    bool act[4] = {true, true, true, true};
    int need = 32;
    int lane = tid & 31, w = tid >> 5;
    for (int shift = 56; shift >= 0; shift -= 8){
        hist[tid] = 0;
        __syncthreads();
        #pragma unroll
        for (int e = 0; e < 4; e++)
            if (e < npt && act[e])
                atomicAdd(&hist[(unsigned)((kv[e] >> shift) & 255)], 1u);
        __syncthreads();
        unsigned h = hist[tid];
        unsigned inc = h;
        #pragma unroll
        for (int off = 1; off < 32; off <<= 1){
            unsigned v = __shfl_down_sync(0xFFFFFFFFu, inc, off);
            if (lane + off < 32) inc += v;
        }
        if (lane == 0) sh[8 + w] = inc;
        __syncthreads();
        unsigned upper = 0;
        #pragma unroll
        for (int ww = 1; ww < 8; ww++) if (ww > w) upper += sh[8 + ww];
        unsigned cge = inc + upper;
        unsigned cgt = cge - h;
        if (cgt < (unsigned)need && cge >= (unsigned)need){
            sh[0] = (unsigned)tid;
            sh[1] = (unsigned)need - cgt;
            sh[2] = (h == (unsigned)need - cgt) ? 1u : 0u;
        }
        __syncthreads();
        unsigned D = sh[0];
        need = (int)sh[1];
        unsigned done = sh[2];
        prefix |= ((unsigned long long)D) << shift;
        if (done) return prefix;
        #pragma unroll
        for (int e = 0; e < 4; e++)
            if (e < npt)
                act[e] = act[e] && (((kv[e] >> shift) & 255) == (unsigned long long)D);
        __syncthreads();
    }
    return prefix;
}

// ---------------- fused SVD + two-level top-k + memory gather ----------------
__global__ __launch_bounds__(256) void select_gather_kernel(const float* __restrict__ core,
                                                            const float* __restrict__ mem,
                                                            float* __restrict__ d_out, int out_size)
{
    __shared__ float rs[1024];
    __shared__ unsigned hist[256];
    __shared__ unsigned sh[16];
    __shared__ int ridx[32], cidx[32];
    __shared__ float gg0[32], gg1[32], fc0[32], fc1[32];
    __shared__ float suv[8];
    __shared__ int cnt;
    __shared__ float sfs[2][TOPK];
    __shared__ int   sfidx[2][TOPK];
    int tok = blockIdx.x, tid = threadIdx.x;
    if (tid == 0){
        float aux = 0.f;
        #pragma unroll
        for (int hh = 0; hh < 2; hh++){
            float u0,u1,t0,t1,ap;
            svd2x2(core, hh, u0, u1, t0, t1, ap);
            suv[hh*4+0]=u0; suv[hh*4+1]=u1; suv[hh*4+2]=t0; suv[hh*4+3]=t1;
            aux += ap;
        }
        if (tok == 0 && out_size > OUT_MAIN) d_out[OUT_MAIN] = aux*0.1f;
    }
    #pragma unroll
    for (int e = 0; e < 4; e++) rs[tid + e*256] = g_sc[(size_t)tok*1024 + tid + e*256];
    __syncthreads();

    for (int h = 0; h < 2; h++){
        float u0 = suv[h*4+0], u1 = suv[h*4+1];
        float t0 = suv[h*4+2], t1 = suv[h*4+3];
        float c00 = core[h*4+0], c01 = core[h*4+1], c10 = core[h*4+2], c11 = core[h*4+3];

        if (tid == 0) cnt = 0;
        unsigned long long kr = pack_key(rs[2*tid]*u0 + rs[2*tid+1]*u1, (unsigned)tid);
        unsigned long long T = radix_select32(&kr, 1, tid, hist, sh);
        if (kr >= T){ int s = atomicAdd(&cnt, 1); ridx[s] = tid; }
        __syncthreads();
        if (tid < 32){
            int mi = ridx[tid];
            float f0 = rs[2*mi], f1 = rs[2*mi+1];
            gg0[tid] = f0*c00 + f1*c10;
            gg1[tid] = f0*c01 + f1*c11;
        }

        if (tid == 0) cnt = 0;
        unsigned long long kc = pack_key(rs[512 + 2*tid]*t0 + rs[512 + 2*tid+1]*t1, (unsigned)tid);
        T = radix_select32(&kc, 1, tid, hist, sh);
        if (kc >= T){ int s = atomicAdd(&cnt, 1); cidx[s] = tid; }
        __syncthreads();
        if (tid < 32){
            int mi = cidx[tid];
            fc0[tid] = rs[512 + 2*mi];
            fc1[tid] = rs[512 + 2*mi+1];
        }
        __syncthreads();

        if (tid == 0) cnt = 0;
        unsigned long long kv[4];
        #pragma unroll
        for (int c = 0; c < 4; c++){
            int p = c*256 + tid;
            int i = p >> 5, j = p & 31;
            float val = gg0[i]*fc0[j] + gg1[i]*fc1[j];
            kv[c] = pack_key(val, (unsigned)p);
        }
        T = radix_select32(kv, 4, tid, hist, sh);
        #pragma unroll
        for (int c = 0; c < 4; c++){
            if (kv[c] >= T){
                int s = atomicAdd(&cnt, 1);
                int p = (int)(0xFFFFFFFFu - (unsigned)(kv[c] & 0xFFFFFFFFu));
                float val = unsortable_f((unsigned)(kv[c] >> 32));
                sfs[h][s]   = 1.f/(1.f + expf(-val));
                sfidx[h][s] = ridx[p >> 5]*NKEY + cidx[p & 31];
            }
        }
        __syncthreads();
    }

    // gather phase
    int h = tid >> 7, t = tid & 127;
    float4 acc = {0.f,0.f,0.f,0.f};
    #pragma unroll 16
    for (int k = 0; k < TOPK; k++){
        const float4* row = (const float4*)(mem + (size_t)sfidx[h][k]*DV);
        float4 v = __ldg(row + t);
        float ww = sfs[h][k];
        acc.x += ww*v.x; acc.y += ww*v.y; acc.z += ww*v.z; acc.w += ww*v.w;
    }
    ((float4*)(d_out + (size_t)tok*1024 + h*DV))[t] = acc;
}

extern "C" void kernel_launch(void* const* d_in, const int* in_sizes, int n_in,
                              void* d_out, int out_size)
{
    const float* tokens  = (const float*)d_in[0];
    const float* rms_w   = (const float*)d_in[1];
    const float* conv_w  = (const float*)d_in[2];
    const float* conv_b  = (const float*)d_in[3];
    const float* wq      = (const float*)d_in[4];
    const float* qln_w   = (const float*)d_in[5];
    const float* keys    = (const float*)d_in[6];
    const float* core    = (const float*)d_in[7];
    const float* mems    = (const float*)d_in[8];
    float* out = (float*)d_out;

    float* x2;    cudaGetSymbolAddress((void**)&x2, g_x2);
    float* qpart; cudaGetSymbolAddress((void**)&qpart, g_qpart);
    float* q;     cudaGetSymbolAddress((void**)&q, g_q);
    float* sc;    cudaGetSymbolAddress((void**)&sc, g_sc);

    conv_kernel<<<TOK/4, 256>>>(tokens, rms_w, conv_w, conv_b);
    gemm_q<<<dim3(1,32,8), 256>>>(x2, wq, qpart);
    ln_kernel<<<TOK/8, 256>>>(qln_w);
    gemm_sc<<<dim3(8,32,1), 256>>>(q, keys, sc);
    select_gather_kernel<<<TOK, 256>>>(core, mems, out, out_size);
}